// round 2
// baseline (speedup 1.0000x reference)
#include <cuda_runtime.h>
#include <math.h>
#include <stdint.h>

// ---------------------------------------------------------------------------
// LSTM + differentiable stack, 259 sequential steps, persistent kernel.
// Phases per step (separated by manual grid barriers, 128 CTAs all resident):
//   P1: split-K GEMM  g_part[ks] += [x_t|r|h] @ [Wih|Whh]^T   (16 n-tiles x 8 k-slices)
//   P2: reduce partials + biases -> gates -> (h,c) update      (1 CTA per batch row)
//   P3: out194 = h @ Wr^T + br                                 (49 CTAs x 4 cols)
//   P4: stack update (suffix sums, A, r_t), V row store,
//       log_softmax output for t >= 129                        (1 CTA per batch row)
// ---------------------------------------------------------------------------

#define BATCH   128
#define HID     512
#define G4      2048
#define INPD    128
#define STKD    64
#define KXIN    192     // 128 (x) + 64 (r)
#define MAXT    259
#define NSTEPS  259
#define KSTART  129     // steps >= 129 have x == 0
#define OCOLS   194

#define GRIDN   128
#define NTHR    256
#define KC      16
#define NCHUNKS 44      // 704 / 16
#define XCHUNKS 8       // chunks 0..7 come from x
#define KSLICES 8
#define BN      128     // gate-column tile
#define ASTRIDE 132     // padded smem row stride (floats), 16B-aligned rows

__device__ float d_h[BATCH * HID];
__device__ float d_c[BATCH * HID];
__device__ float d_r[BATCH * STKD];
__device__ float d_s[BATCH * MAXT];
__device__ float d_V[BATCH * MAXT * STKD];
__device__ float d_part[KSLICES * BATCH * G4];
__device__ float d_o194[BATCH * OCOLS];
__device__ unsigned g_bar;

__device__ __forceinline__ float sigf(float x) { return 1.0f / (1.0f + expf(-x)); }

// Manual grid barrier: all GRIDN CTAs are co-resident (GRIDN <= #SMs).
__device__ __forceinline__ void grid_sync(unsigned &n) {
    __syncthreads();
    n += (unsigned)GRIDN;
    if (threadIdx.x == 0) {
        __threadfence();
        atomicAdd(&g_bar, 1u);
        while (*((volatile unsigned *)&g_bar) < n) {
            __nanosleep(32);
        }
        __threadfence();
    }
    __syncthreads();
}

// ------------------------- Phase 1: gate GEMM (split-K) --------------------
__device__ __forceinline__ void gemm1_phase(int t,
                                            const float *__restrict__ x,
                                            const float *__restrict__ Wih,
                                            const float *__restrict__ Whh,
                                            float *sm) {
    float *As = sm;                   // [KC][ASTRIDE]
    float *Ws = sm + KC * ASTRIDE;    // [KC][ASTRIDE]

    const int tid = threadIdx.x;
    const int bid = blockIdx.x;
    const int nt  = bid >> 3;   // 0..15 : gate-column tile
    const int ks  = bid & 7;    // 0..7  : k slice

    const int cbeg = (t < KSTART) ? 0 : XCHUNKS;
    const int nch  = NCHUNKS - cbeg;
    const int c0   = cbeg + (ks * nch) / KSLICES;
    const int c1   = cbeg + ((ks + 1) * nch) / KSLICES;

    const int tx = tid & 15;    // col group
    const int ty = tid >> 4;    // row (b) group

    float acc[8][8];
#pragma unroll
    for (int i = 0; i < 8; ++i)
#pragma unroll
        for (int j = 0; j < 8; ++j) acc[i][j] = 0.0f;

    for (int c = c0; c < c1; ++c) {
        const int kb = c * KC;
        // ---- load A tile (16 k x 128 b), transposed into smem ----
#pragma unroll
        for (int q = 0; q < 2; ++q) {
            int idx = tid + q * NTHR;       // 0..511
            int b   = idx >> 2;
            int f4  = idx & 3;
            const float *src;
            if (c < XCHUNKS)      src = x + ((size_t)t * BATCH + b) * INPD + kb;
            else if (c < 12)      src = d_r + b * STKD + (kb - 128);
            else                  src = d_h + b * HID + (kb - 192);
            float4 v = *(const float4 *)(src + f4 * 4);
            As[(f4 * 4 + 0) * ASTRIDE + b] = v.x;
            As[(f4 * 4 + 1) * ASTRIDE + b] = v.y;
            As[(f4 * 4 + 2) * ASTRIDE + b] = v.z;
            As[(f4 * 4 + 3) * ASTRIDE + b] = v.w;
        }
        // ---- load W tile (16 k x 128 cols), transposed into smem ----
#pragma unroll
        for (int q = 0; q < 2; ++q) {
            int idx  = tid + q * NTHR;
            int col  = idx >> 2;
            int f4   = idx & 3;
            int gcol = nt * BN + col;
            const float *src;
            if (c < 12) src = Wih + (size_t)gcol * KXIN + kb;
            else        src = Whh + (size_t)gcol * HID + (kb - 192);
            float4 v = *(const float4 *)(src + f4 * 4);
            Ws[(f4 * 4 + 0) * ASTRIDE + col] = v.x;
            Ws[(f4 * 4 + 1) * ASTRIDE + col] = v.y;
            Ws[(f4 * 4 + 2) * ASTRIDE + col] = v.z;
            Ws[(f4 * 4 + 3) * ASTRIDE + col] = v.w;
        }
        __syncthreads();
#pragma unroll
        for (int kk = 0; kk < KC; ++kk) {
            const float4 *ar = (const float4 *)(As + kk * ASTRIDE);
            const float4 *wr = (const float4 *)(Ws + kk * ASTRIDE);
            float4 a0 = ar[ty * 2], a1 = ar[ty * 2 + 1];
            float4 w0 = wr[tx * 2], w1 = wr[tx * 2 + 1];
            float av[8] = {a0.x, a0.y, a0.z, a0.w, a1.x, a1.y, a1.z, a1.w};
            float wv[8] = {w0.x, w0.y, w0.z, w0.w, w1.x, w1.y, w1.z, w1.w};
#pragma unroll
            for (int i = 0; i < 8; ++i)
#pragma unroll
                for (int j = 0; j < 8; ++j)
                    acc[i][j] = fmaf(av[i], wv[j], acc[i][j]);
        }
        __syncthreads();
    }
    // ---- store partials ----
#pragma unroll
    for (int i = 0; i < 8; ++i) {
        int b = ty * 8 + i;
        float *dst = d_part + ((size_t)ks * BATCH + b) * G4 + nt * BN + tx * 8;
        *(float4 *)(dst)     = make_float4(acc[i][0], acc[i][1], acc[i][2], acc[i][3]);
        *(float4 *)(dst + 4) = make_float4(acc[i][4], acc[i][5], acc[i][6], acc[i][7]);
    }
}

// ------------------- Phase 2: reduce + LSTM cell update --------------------
__device__ __forceinline__ void cell_phase(const float *__restrict__ bih,
                                           const float *__restrict__ bhh) {
    const int b = blockIdx.x;
    for (int j = threadIdx.x; j < HID; j += NTHR) {
        float g[4];
#pragma unroll
        for (int m = 0; m < 4; ++m) {
            int col = m * HID + j;
            float s = bih[col] + bhh[col];
#pragma unroll
            for (int ksl = 0; ksl < KSLICES; ++ksl)
                s += d_part[((size_t)ksl * BATCH + b) * G4 + col];
            g[m] = s;
        }
        float ig = sigf(g[0]);
        float fg = sigf(g[1]);
        float gg = tanhf(g[2]);
        float og = sigf(g[3]);
        float c  = d_c[b * HID + j];
        float c2 = fg * c + ig * gg;
        float h2 = og * tanhf(c2);
        d_c[b * HID + j] = c2;
        d_h[b * HID + j] = h2;
    }
}

// ------------------------- Phase 3: readout GEMM ----------------------------
__device__ __forceinline__ void gemm2_phase(const float *__restrict__ Wr,
                                            const float *__restrict__ br,
                                            float *sm) {
    const int bid = blockIdx.x;
    if (bid >= 49) return;
    const int tid = threadIdx.x;
    const int n0  = bid * 4;
    float *Wsr = sm;  // [4][512]
    for (int idx = tid; idx < 4 * HID; idx += NTHR) {
        int cc = idx >> 9;
        int k  = idx & 511;
        int n  = n0 + cc;
        Wsr[idx] = (n < OCOLS) ? Wr[(size_t)n * HID + k] : 0.0f;
    }
    __syncthreads();

    const int b  = tid >> 1;
    const int kh = tid & 1;
    const float4 *hv = (const float4 *)(d_h + b * HID + kh * 256);
    float acc[4] = {0.f, 0.f, 0.f, 0.f};
#pragma unroll 8
    for (int k4 = 0; k4 < 64; ++k4) {
        float4 h4 = hv[k4];
        int kk = kh * 256 + k4 * 4;
#pragma unroll
        for (int cc = 0; cc < 4; ++cc) {
            const float *w = Wsr + cc * HID + kk;
            acc[cc] += h4.x * w[0] + h4.y * w[1] + h4.z * w[2] + h4.w * w[3];
        }
    }
#pragma unroll
    for (int cc = 0; cc < 4; ++cc)
        acc[cc] += __shfl_down_sync(0xffffffffu, acc[cc], 1);
    if (kh == 0) {
#pragma unroll
        for (int cc = 0; cc < 4; ++cc) {
            int n = n0 + cc;
            if (n < OCOLS) d_o194[b * OCOLS + n] = acc[cc] + br[n];
        }
    }
    __syncthreads();
}

// ---------------- Phase 4: stack update + log_softmax output ---------------
__device__ __forceinline__ void stack_phase(int t, float *__restrict__ out, float *sm) {
    const int b   = blockIdx.x;
    const int tid = threadIdx.x;
    float *ss   = sm;           // 288
    float *ssuf = sm + 288;     // 288
    float *sA   = sm + 576;     // 288
    float *so   = sm + 864;     // 208
    float *csum = sm + 1072;    // 16
    float *sred = sm + 1088;    // 256

    if (tid < OCOLS) so[tid] = d_o194[b * OCOLS + tid];
    for (int i = tid; i < 288; i += NTHR)
        ss[i] = (i < MAXT) ? d_s[b * MAXT + i] : 0.0f;
    __syncthreads();

    if (tid < STKD) d_V[((size_t)b * MAXT + t) * STKD + tid] = so[tid];
    float u  = sigf(so[192]);
    float dd = sigf(so[193]);

    const int lane = tid & 31, wid = tid >> 5;
    // per-32-chunk inclusive suffix scans
    for (int cch = wid; cch < 9; cch += 8) {
        float v = ss[cch * 32 + lane];
#pragma unroll
        for (int o = 1; o < 32; o <<= 1) {
            float tv = __shfl_down_sync(0xffffffffu, v, o);
            if (lane + o < 32) v += tv;
        }
        ssuf[cch * 32 + lane] = v;
        if (lane == 0) csum[cch] = v;
    }
    __syncthreads();
    if (wid == 0) {
        float tv = (lane < 9) ? csum[lane] : 0.0f;
        float vv = tv;
#pragma unroll
        for (int o = 1; o < 16; o <<= 1) {
            float sh = __shfl_down_sync(0xffffffffu, vv, o);
            if (lane + o < 16) vv += sh;
        }
        if (lane < 9) csum[lane] = vv - tv;   // strict suffix of chunk totals
    }
    __syncthreads();

    for (int i = tid; i < MAXT; i += NTHR) {
        float si   = ss[i];
        float prod = ssuf[i] + csum[i >> 5] - si;     // sum_{j>i} s[j]
        float sp   = fmaxf(0.0f, si - fmaxf(0.0f, u - prod));
        if (i == t) sp = dd;
        float inner = fmaxf(0.0f, 1.0f - prod - sp);
        sA[i] = fminf(sp, inner);
        if (i <= t) d_s[b * MAXT + i] = sp;
    }
    __syncthreads();

    // r_t[d] = sum_{i<=t} A[i] * V[b][i][d]
    const int dcol = tid & 63, q = tid >> 6;
    float acc = 0.0f;
    for (int i = q; i <= t; i += 4)
        acc += sA[i] * d_V[((size_t)b * MAXT + i) * STKD + dcol];
    sred[q * 64 + dcol] = acc;
    __syncthreads();
    if (tid < STKD)
        d_r[b * STKD + tid] = sred[tid] + sred[64 + tid] + sred[128 + tid] + sred[192 + tid];

    // log_softmax over ot for the second scan
    if (t >= KSTART) {
        __syncthreads();
        float v = (tid < INPD) ? so[STKD + tid] : -1e30f;
        float m = v;
#pragma unroll
        for (int o = 16; o; o >>= 1) m = fmaxf(m, __shfl_xor_sync(0xffffffffu, m, o));
        if (lane == 0) csum[wid] = m;
        __syncthreads();
        float mm = csum[0];
#pragma unroll
        for (int w = 1; w < 8; ++w) mm = fmaxf(mm, csum[w]);
        float e = (tid < INPD) ? expf(v - mm) : 0.0f;
#pragma unroll
        for (int o = 16; o; o >>= 1) e += __shfl_xor_sync(0xffffffffu, e, o);
        if (lane == 0) csum[8 + wid] = e;
        __syncthreads();
        float tot = 0.0f;
#pragma unroll
        for (int w = 0; w < 8; ++w) tot += csum[8 + w];
        float ls = logf(tot);
        if (tid < INPD)
            out[(((size_t)(t - KSTART)) * BATCH + b) * INPD + tid] = v - mm - ls;
    }
}

// ------------------------------- main kernel --------------------------------
__global__ void __launch_bounds__(NTHR, 1)
lstm_stack_kernel(const float *__restrict__ x,
                  const float *__restrict__ Wih, const float *__restrict__ bih,
                  const float *__restrict__ Whh, const float *__restrict__ bhh,
                  const float *__restrict__ Wr, const float *__restrict__ br,
                  float *__restrict__ out) {
    __shared__ __align__(16) float sm[4480];
    unsigned n = 0;
    for (int t = 0; t < NSTEPS; ++t) {
        gemm1_phase(t, x, Wih, Whh, sm);
        grid_sync(n);
        cell_phase(bih, bhh);
        grid_sync(n);
        gemm2_phase(Wr, br, sm);
        grid_sync(n);
        stack_phase(t, out, sm);
        grid_sync(n);
    }
}

extern "C" void kernel_launch(void *const *d_in, const int *in_sizes, int n_in,
                              void *d_out, int out_size) {
    (void)in_sizes; (void)n_in; (void)out_size;
    const float *x   = (const float *)d_in[0];
    const float *Wih = (const float *)d_in[1];
    const float *bih = (const float *)d_in[2];
    const float *Whh = (const float *)d_in[3];
    const float *bhh = (const float *)d_in[4];
    const float *Wr  = (const float *)d_in[5];
    const float *br  = (const float *)d_in[6];
    float *out = (float *)d_out;

    void *p;
    cudaGetSymbolAddress(&p, d_h);   cudaMemsetAsync(p, 0, sizeof(float) * BATCH * HID);
    cudaGetSymbolAddress(&p, d_c);   cudaMemsetAsync(p, 0, sizeof(float) * BATCH * HID);
    cudaGetSymbolAddress(&p, d_r);   cudaMemsetAsync(p, 0, sizeof(float) * BATCH * STKD);
    cudaGetSymbolAddress(&p, d_s);   cudaMemsetAsync(p, 0, sizeof(float) * BATCH * MAXT);
    cudaGetSymbolAddress(&p, g_bar); cudaMemsetAsync(p, 0, sizeof(unsigned));

    lstm_stack_kernel<<<GRIDN, NTHR>>>(x, Wih, bih, Whh, bhh, Wr, br, out);
}